// round 5
// baseline (speedup 1.0000x reference)
#include <cuda_runtime.h>
#include <math.h>

// S4D real SSM:  y[l,c] = sum_{j<=l} K[l-j,c] x[j,c],
// K[l,c] = sum_s C*Bd*exp(l*A*dt)  ==  diagonal recurrence
//   h[l,c,s] = a*h[l-1,c,s] + x[l,c]   (a = exp(A*dt), Bd folded into CB)
//   y[l,c]   = sum_s CB[c,s]*h[l,c,s]
// computed via a 3-phase chunked scan over L.

#define LEN   4096
#define CH    512
#define S     64
#define NC    64            // chunks over L
#define LC    64            // chunk length (NC*LC == LEN)
#define CS    (CH*S)        // 32768 states
#define DT    (1.0/4096.0)

// scratch (static device globals; no allocation)
__device__ float g_a [CS];   // per-state decay exp(A*dt)
__device__ float g_cb[CS];   // C * Bd
__device__ float g_dc[CS];   // chunk decay exp(A*dt*LC)
__device__ float g_v [NC*CS];   // per-chunk state contribution (zero init state)
__device__ float g_h0[NC*CS];   // per-chunk initial state (after prefix scan)

// ---------------------------------------------------------------- precompute
__global__ void precompute_k(const float* __restrict__ lognegA,
                             const float* __restrict__ B,
                             const float* __restrict__ C)
{
    int i = blockIdx.x * blockDim.x + threadIdx.x;
    if (i >= CS) return;
    double A  = -exp((double)lognegA[i]);        // strictly negative
    double ad = A * DT;
    double Bd = expm1(ad) / A * (double)B[i];    // (exp(A dt)-1)*B/A, stable
    g_a [i] = (float)exp(ad);
    g_cb[i] = (float)((double)C[i] * Bd);
    g_dc[i] = (float)exp(ad * (double)LC);
}

// ---------------------------------------------------------------- pass A
// grid (NC, CH/32), block 1024 (32 warps). Warp w owns channel cbase+w,
// lane owns states {lane, lane+32}. Computes chunk contribution with h0=0.
__global__ __launch_bounds__(1024, 1)
void passA_k(const float* __restrict__ x)
{
    __shared__ float sx[LC][32];
    const int chunk = blockIdx.x;
    const int cbase = blockIdx.y * 32;
    const int tid   = threadIdx.x;
    const int w     = tid >> 5;
    const int lane  = tid & 31;
    const int l0    = chunk * LC;

    // coalesced x tile load: [LC rows][32 channels]
    #pragma unroll
    for (int i = tid; i < LC * 32; i += 1024) {
        int lr = i >> 5, cc = i & 31;
        sx[lr][cc] = x[(l0 + lr) * CH + cbase + cc];
    }
    __syncthreads();

    const int c    = cbase + w;
    const int base = c * S;
    const float a0 = g_a[base + lane];
    const float a1 = g_a[base + lane + 32];
    float h0 = 0.f, h1 = 0.f;
    #pragma unroll
    for (int l = 0; l < LC; l++) {
        float xv = sx[l][w];
        h0 = fmaf(a0, h0, xv);
        h1 = fmaf(a1, h1, xv);
    }
    g_v[chunk * CS + base + lane]      = h0;
    g_v[chunk * CS + base + lane + 32] = h1;
}

// ---------------------------------------------------------------- chunk scan
// one thread per state: serial prefix over NC chunks.
__global__ void scan_k()
{
    int i = blockIdx.x * blockDim.x + threadIdx.x;
    if (i >= CS) return;
    const float d = g_dc[i];
    float h = 0.f;
    #pragma unroll 8
    for (int k = 0; k < NC; k++) {
        g_h0[k * CS + i] = h;
        h = fmaf(d, h, g_v[k * CS + i]);
    }
}

// ---------------------------------------------------------------- pass C
// Same layout as pass A, but starts from g_h0 and produces y.
// Outputs for 32 steps are buffered in registers and reduced across the warp
// with a register-halving butterfly (31 shfl for 32 outputs), then staged
// through shared memory for coalesced [L,CH] stores.
__global__ __launch_bounds__(1024, 1)
void passC_k(const float* __restrict__ x, float* __restrict__ y)
{
    __shared__ float sx[LC][32];
    __shared__ float sy[32][33];          // padded: conflict-free transpose
    const int chunk = blockIdx.x;
    const int cbase = blockIdx.y * 32;
    const int tid   = threadIdx.x;
    const int w     = tid >> 5;
    const int lane  = tid & 31;
    const int l0    = chunk * LC;

    #pragma unroll
    for (int i = tid; i < LC * 32; i += 1024) {
        int lr = i >> 5, cc = i & 31;
        sx[lr][cc] = x[(l0 + lr) * CH + cbase + cc];
    }
    __syncthreads();

    const int c    = cbase + w;
    const int base = c * S;
    const float a0  = g_a [base + lane];
    const float a1  = g_a [base + lane + 32];
    const float cb0 = g_cb[base + lane];
    const float cb1 = g_cb[base + lane + 32];
    float h0 = g_h0[chunk * CS + base + lane];
    float h1 = g_h0[chunk * CS + base + lane + 32];

    #pragma unroll
    for (int half = 0; half < LC / 32; half++) {
        float p[32];
        #pragma unroll
        for (int j = 0; j < 32; j++) {
            float xv = sx[half * 32 + j][w];
            h0 = fmaf(a0, h0, xv);
            h1 = fmaf(a1, h1, xv);
            p[j] = fmaf(cb1, h1, cb0 * h0);   // partial output for step j
        }
        // butterfly merge: after 5 stages, lane i holds sum over lanes of p[i]
        #pragma unroll
        for (int d = 16; d >= 1; d >>= 1) {
            #pragma unroll
            for (int k = 0; k < d; k++) {
                bool  hi   = (lane & d) != 0;
                float send = hi ? p[k] : p[k + d];
                float got  = __shfl_xor_sync(0xffffffffu, send, d);
                p[k] = (hi ? p[k + d] : p[k]) + got;
            }
        }
        sy[lane][w] = p[0];                   // y(l0+half*32+lane, channel c)
        __syncthreads();
        // coalesced store: each warp writes one l-row of 32 channels (128B)
        y[(l0 + half * 32 + w) * CH + cbase + lane] = sy[w][lane];
        __syncthreads();
    }
}

// ---------------------------------------------------------------- launch
extern "C" void kernel_launch(void* const* d_in, const int* in_sizes, int n_in,
                              void* d_out, int out_size)
{
    const float* x       = (const float*)d_in[0];
    const float* lognegA = (const float*)d_in[1];
    const float* B       = (const float*)d_in[2];
    const float* C       = (const float*)d_in[3];
    float*       y       = (float*)d_out;

    precompute_k<<<(CS + 255) / 256, 256>>>(lognegA, B, C);
    dim3 grid(NC, CH / 32);
    passA_k<<<grid, 1024>>>(x);
    scan_k<<<(CS + 255) / 256, 256>>>();
    passC_k<<<grid, 1024>>>(x, y);
}

// round 6
// speedup vs baseline: 1.1654x; 1.1654x over previous
#include <cuda_runtime.h>
#include <math.h>

// S4D real SSM via chunked parallel scan, v2:
//  - tiling: 4 lanes/channel x 16 states/lane (8 f32x2 pairs), 8 channels/warp
//  - packed fma.rn.f32x2 for state update + output accumulation (2x FMA tput)
//  - 4096 total warps -> single wave on 148 SMs (was 7 waves)

#define LEN   4096
#define CH    512
#define S     64
#define NC    64            // chunks over L
#define LC    64            // chunk length
#define CS    (CH*S)        // 32768 states
#define DT    (1.0/4096.0)

#define LPC   4             // lanes per channel
#define SPL   16            // states per lane
#define NPK   8             // packed f32x2 pairs per lane
#define CPW   8             // channels per warp
#define CPB   128           // channels per block (16 warps * 8)

typedef unsigned long long ull;

__device__ float g_a [CS];      // exp(A*dt)
__device__ float g_cb[CS];      // C * Bd
__device__ float g_dc[CS];      // exp(A*dt*LC)
__device__ float g_v [NC*CS];   // per-chunk contribution (h0 = 0)
__device__ float g_h0[NC*CS];   // per-chunk initial state

// ---- packed f32x2 helpers (Blackwell FFMA2 path, PTX-only) ----------------
__device__ __forceinline__ ull pack2(float x, float y) {
    ull r; asm("mov.b64 %0, {%1, %2};" : "=l"(r) : "f"(x), "f"(y)); return r;
}
__device__ __forceinline__ ull fma2(ull a, ull b, ull c) {
    ull d; asm("fma.rn.f32x2 %0, %1, %2, %3;" : "=l"(d) : "l"(a), "l"(b), "l"(c)); return d;
}
__device__ __forceinline__ ull mul2(ull a, ull b) {
    ull d; asm("mul.rn.f32x2 %0, %1, %2;" : "=l"(d) : "l"(a), "l"(b)); return d;
}
__device__ __forceinline__ float hsum2(ull v) {
    float lo, hi; asm("mov.b64 {%0, %1}, %2;" : "=f"(lo), "=f"(hi) : "l"(v));
    return lo + hi;
}

// ---------------------------------------------------------------- precompute
__global__ void precompute_k(const float* __restrict__ lognegA,
                             const float* __restrict__ B,
                             const float* __restrict__ C)
{
    int i = blockIdx.x * blockDim.x + threadIdx.x;
    if (i >= CS) return;
    double A  = -exp((double)lognegA[i]);
    double ad = A * DT;
    double Bd = expm1(ad) / A * (double)B[i];
    g_a [i] = (float)exp(ad);
    g_cb[i] = (float)((double)C[i] * Bd);
    g_dc[i] = (float)exp(ad * (double)LC);
}

// ---------------------------------------------------------------- pass A
// grid (NC, CH/CPB), block 512. Lane owns 16 states (8 pairs) of one channel;
// computes the chunk contribution with zero initial state.
__global__ __launch_bounds__(512, 2)
void passA_k(const float* __restrict__ x)
{
    __shared__ float sx[LC][CPB];
    const int chunk = blockIdx.x;
    const int cbase = blockIdx.y * CPB;
    const int tid   = threadIdx.x;
    const int w     = tid >> 5;
    const int lane  = tid & 31;
    const int g     = lane >> 2;      // channel within warp
    const int q     = lane & 3;       // lane within channel group
    const int l0    = chunk * LC;

    #pragma unroll
    for (int i = tid; i < LC * CPB; i += 512) {
        int lr = i >> 7, cc = i & (CPB - 1);
        sx[lr][cc] = x[(l0 + lr) * CH + cbase + cc];
    }
    __syncthreads();

    const int c     = cbase + w * CPW + g;
    const int sbase = c * S + q * SPL;
    const int chl   = w * CPW + g;

    ull a[NPK], h[NPK];
    const ull* aP = reinterpret_cast<const ull*>(g_a + sbase);
    #pragma unroll
    for (int k = 0; k < NPK; k++) { a[k] = aP[k]; h[k] = 0ull; }

    #pragma unroll
    for (int l = 0; l < LC; l++) {
        float xv = sx[l][chl];
        ull   xx = pack2(xv, xv);
        #pragma unroll
        for (int k = 0; k < NPK; k++) h[k] = fma2(a[k], h[k], xx);
    }

    ull* vP = reinterpret_cast<ull*>(g_v + chunk * CS + sbase);
    #pragma unroll
    for (int k = 0; k < NPK; k++) vP[k] = h[k];
}

// ---------------------------------------------------------------- chunk scan
__global__ void scan_k()
{
    int i = blockIdx.x * blockDim.x + threadIdx.x;
    if (i >= CS) return;
    const float d = g_dc[i];
    float h = 0.f;
    #pragma unroll 8
    for (int k = 0; k < NC; k++) {
        g_h0[k * CS + i] = h;
        h = fmaf(d, h, g_v[k * CS + i]);
    }
}

// ---------------------------------------------------------------- pass C
// Same tiling; starts from g_h0 and emits y. Outputs buffered 4 steps, then
// a 2-stage butterfly within each 4-lane group (3 warp-shfl serve 8 channels
// x 4 steps), staged through smem for coalesced [L,CH] stores.
__global__ __launch_bounds__(512, 2)
void passC_k(const float* __restrict__ x, float* __restrict__ y)
{
    __shared__ float sx[LC][CPB];
    __shared__ float sy[16][CPB + 4];
    const int chunk = blockIdx.x;
    const int cbase = blockIdx.y * CPB;
    const int tid   = threadIdx.x;
    const int w     = tid >> 5;
    const int lane  = tid & 31;
    const int g     = lane >> 2;
    const int q     = lane & 3;
    const int l0    = chunk * LC;

    #pragma unroll
    for (int i = tid; i < LC * CPB; i += 512) {
        int lr = i >> 7, cc = i & (CPB - 1);
        sx[lr][cc] = x[(l0 + lr) * CH + cbase + cc];
    }
    __syncthreads();

    const int c     = cbase + w * CPW + g;
    const int sbase = c * S + q * SPL;
    const int chl   = w * CPW + g;

    ull a[NPK], cb[NPK], h[NPK];
    const ull* aP  = reinterpret_cast<const ull*>(g_a  + sbase);
    const ull* cbP = reinterpret_cast<const ull*>(g_cb + sbase);
    const ull* hP  = reinterpret_cast<const ull*>(g_h0 + chunk * CS + sbase);
    #pragma unroll
    for (int k = 0; k < NPK; k++) { a[k] = aP[k]; cb[k] = cbP[k]; h[k] = hP[k]; }

    #pragma unroll
    for (int r = 0; r < 16; r++) {
        float p[4];
        #pragma unroll
        for (int j = 0; j < 4; j++) {
            float xv = sx[r * 4 + j][chl];
            ull   xx = pack2(xv, xv);
            #pragma unroll
            for (int k = 0; k < NPK; k++) h[k] = fma2(a[k], h[k], xx);
            ull acc = mul2(cb[0], h[0]);
            #pragma unroll
            for (int k = 1; k < NPK; k++) acc = fma2(cb[k], h[k], acc);
            p[j] = hsum2(acc);
        }
        // butterfly within the 4-lane group: after it, lane q holds step r*4+q
        #pragma unroll
        for (int d = 2; d >= 1; d >>= 1) {
            #pragma unroll
            for (int k = 0; k < d; k++) {
                bool  hi   = (q & d) != 0;
                float send = hi ? p[k] : p[k + d];
                float got  = __shfl_xor_sync(0xffffffffu, send, d);
                p[k] = (hi ? p[k + d] : p[k]) + got;
            }
        }
        sy[(r & 3) * 4 + q][chl] = p[0];

        if ((r & 3) == 3) {
            __syncthreads();
            const int fbase = (r >> 2) * 16;
            #pragma unroll
            for (int i = tid; i < 16 * CPB; i += 512) {
                int lr = i >> 7, cc = i & (CPB - 1);
                y[(l0 + fbase + lr) * CH + cbase + cc] = sy[lr][cc];
            }
            __syncthreads();
        }
    }
}

// ---------------------------------------------------------------- launch
extern "C" void kernel_launch(void* const* d_in, const int* in_sizes, int n_in,
                              void* d_out, int out_size)
{
    const float* x       = (const float*)d_in[0];
    const float* lognegA = (const float*)d_in[1];
    const float* B       = (const float*)d_in[2];
    const float* C       = (const float*)d_in[3];
    float*       y       = (float*)d_out;

    precompute_k<<<(CS + 255) / 256, 256>>>(lognegA, B, C);
    dim3 grid(NC, CH / CPB);
    passA_k<<<grid, 512>>>(x);
    scan_k<<<(CS + 255) / 256, 256>>>();
    passC_k<<<grid, 512>>>(x, y);
}

// round 7
// speedup vs baseline: 1.3491x; 1.1576x over previous
#include <cuda_runtime.h>
#include <math.h>

// S4D real SSM via chunked parallel scan, v3:
//  - tiling: 8 lanes/channel x 8 states/lane (4 f32x2 pairs), 4 channels/warp
//  - packed fma.rn.f32x2 state update + output accumulation
//  - passC: barrier-free mainloop, direct STG of butterfly outputs
//  - 256-thread blocks, 5-6 blocks/SM residency

#define LEN   4096
#define CH    512
#define S     64
#define NC    64            // chunks over L
#define LC    64            // chunk length
#define CS    (CH*S)        // 32768 states
#define DT    (1.0/4096.0)

#define SPL   8             // states per lane
#define NPK   4             // packed f32x2 pairs per lane
#define CPW   4             // channels per warp
#define CPB   32            // channels per block (8 warps * 4)

typedef unsigned long long ull;

__device__ float g_a [CS];      // exp(A*dt)
__device__ float g_cb[CS];      // C * Bd
__device__ float g_dc[CS];      // exp(A*dt*LC)
__device__ float g_v [NC*CS];   // per-chunk contribution (h0 = 0)
__device__ float g_h0[NC*CS];   // per-chunk initial state

// ---- packed f32x2 helpers (Blackwell FFMA2 path, PTX-only) ----------------
__device__ __forceinline__ ull pack2(float x, float y) {
    ull r; asm("mov.b64 %0, {%1, %2};" : "=l"(r) : "f"(x), "f"(y)); return r;
}
__device__ __forceinline__ ull fma2(ull a, ull b, ull c) {
    ull d; asm("fma.rn.f32x2 %0, %1, %2, %3;" : "=l"(d) : "l"(a), "l"(b), "l"(c)); return d;
}
__device__ __forceinline__ ull mul2(ull a, ull b) {
    ull d; asm("mul.rn.f32x2 %0, %1, %2;" : "=l"(d) : "l"(a), "l"(b)); return d;
}
__device__ __forceinline__ float hsum2(ull v) {
    float lo, hi; asm("mov.b64 {%0, %1}, %2;" : "=f"(lo), "=f"(hi) : "l"(v));
    return lo + hi;
}

// ---------------------------------------------------------------- precompute
__global__ void precompute_k(const float* __restrict__ lognegA,
                             const float* __restrict__ B,
                             const float* __restrict__ C)
{
    int i = blockIdx.x * blockDim.x + threadIdx.x;
    if (i >= CS) return;
    double A  = -exp((double)lognegA[i]);
    double ad = A * DT;
    double Bd = expm1(ad) / A * (double)B[i];
    g_a [i] = (float)exp(ad);
    g_cb[i] = (float)((double)C[i] * Bd);
    g_dc[i] = (float)exp(ad * (double)LC);
}

// ---------------------------------------------------------------- pass A
// grid (NC, CH/CPB), block 256 (8 warps). Lane owns 8 states (4 pairs) of one
// channel; computes the chunk contribution with zero initial state.
__global__ __launch_bounds__(256, 6)
void passA_k(const float* __restrict__ x)
{
    __shared__ float sx[LC][CPB];
    const int chunk = blockIdx.x;
    const int cbase = blockIdx.y * CPB;
    const int tid   = threadIdx.x;
    const int w     = tid >> 5;
    const int lane  = tid & 31;
    const int g     = lane >> 3;      // channel within warp (0..3)
    const int q     = lane & 7;       // lane within channel group (0..7)
    const int l0    = chunk * LC;

    #pragma unroll
    for (int i = tid; i < LC * CPB; i += 256) {
        int lr = i >> 5, cc = i & (CPB - 1);
        sx[lr][cc] = x[(l0 + lr) * CH + cbase + cc];
    }
    __syncthreads();

    const int c     = cbase + w * CPW + g;
    const int sbase = c * S + q * SPL;
    const int chl   = w * CPW + g;

    ull a[NPK], h[NPK];
    const ull* aP = reinterpret_cast<const ull*>(g_a + sbase);
    #pragma unroll
    for (int k = 0; k < NPK; k++) { a[k] = aP[k]; h[k] = 0ull; }

    #pragma unroll
    for (int l = 0; l < LC; l++) {
        float xv = sx[l][chl];
        ull   xx = pack2(xv, xv);
        #pragma unroll
        for (int k = 0; k < NPK; k++) h[k] = fma2(a[k], h[k], xx);
    }

    ull* vP = reinterpret_cast<ull*>(g_v + chunk * CS + sbase);
    #pragma unroll
    for (int k = 0; k < NPK; k++) vP[k] = h[k];
}

// ---------------------------------------------------------------- chunk scan
__global__ void scan_k()
{
    int i = blockIdx.x * blockDim.x + threadIdx.x;
    if (i >= CS) return;
    const float d = g_dc[i];
    float h = 0.f;
    #pragma unroll 8
    for (int k = 0; k < NC; k++) {
        g_h0[k * CS + i] = h;
        h = fmaf(d, h, g_v[k * CS + i]);
    }
}

// ---------------------------------------------------------------- pass C
// Same tiling; starts from g_h0 and emits y. Outputs buffered 8 steps, then a
// 3-stage register-halving butterfly within each 8-lane group (7 warp-shfl
// serve 4 channels x 8 steps); lane q then holds the finished output for step
// r*8+q of its channel and stores it directly (16B-aligned 4-channel runs).
// No barriers after the tile load.
__global__ __launch_bounds__(256, 5)
void passC_k(const float* __restrict__ x, float* __restrict__ y)
{
    __shared__ float sx[LC][CPB];
    const int chunk = blockIdx.x;
    const int cbase = blockIdx.y * CPB;
    const int tid   = threadIdx.x;
    const int w     = tid >> 5;
    const int lane  = tid & 31;
    const int g     = lane >> 3;
    const int q     = lane & 7;
    const int l0    = chunk * LC;

    #pragma unroll
    for (int i = tid; i < LC * CPB; i += 256) {
        int lr = i >> 5, cc = i & (CPB - 1);
        sx[lr][cc] = x[(l0 + lr) * CH + cbase + cc];
    }
    __syncthreads();

    const int c     = cbase + w * CPW + g;
    const int sbase = c * S + q * SPL;
    const int chl   = w * CPW + g;

    ull a[NPK], cb[NPK], h[NPK];
    const ull* aP  = reinterpret_cast<const ull*>(g_a  + sbase);
    const ull* cbP = reinterpret_cast<const ull*>(g_cb + sbase);
    const ull* hP  = reinterpret_cast<const ull*>(g_h0 + chunk * CS + sbase);
    #pragma unroll
    for (int k = 0; k < NPK; k++) { a[k] = aP[k]; cb[k] = cbP[k]; h[k] = hP[k]; }

    #pragma unroll
    for (int r = 0; r < LC / 8; r++) {
        float p[8];
        #pragma unroll
        for (int j = 0; j < 8; j++) {
            float xv = sx[r * 8 + j][chl];
            ull   xx = pack2(xv, xv);
            #pragma unroll
            for (int k = 0; k < NPK; k++) h[k] = fma2(a[k], h[k], xx);
            ull acc = mul2(cb[0], h[0]);
            #pragma unroll
            for (int k = 1; k < NPK; k++) acc = fma2(cb[k], h[k], acc);
            p[j] = hsum2(acc);
        }
        // 3-stage register-halving butterfly over the 8-lane group:
        // afterwards lane q holds sum over the group of p[q]
        #pragma unroll
        for (int d = 4; d >= 1; d >>= 1) {
            #pragma unroll
            for (int k = 0; k < d; k++) {
                bool  hi   = (q & d) != 0;
                float send = hi ? p[k] : p[k + d];
                float got  = __shfl_xor_sync(0xffffffffu, send, d);
                p[k] = (hi ? p[k + d] : p[k]) + got;
            }
        }
        y[(l0 + r * 8 + q) * CH + c] = p[0];
    }
}

// ---------------------------------------------------------------- launch
extern "C" void kernel_launch(void* const* d_in, const int* in_sizes, int n_in,
                              void* d_out, int out_size)
{
    const float* x       = (const float*)d_in[0];
    const float* lognegA = (const float*)d_in[1];
    const float* B       = (const float*)d_in[2];
    const float* C       = (const float*)d_in[3];
    float*       y       = (float*)d_out;

    precompute_k<<<(CS + 255) / 256, 256>>>(lognegA, B, C);
    dim3 grid(NC, CH / CPB);
    passA_k<<<grid, 256>>>(x);
    scan_k<<<(CS + 255) / 256, 256>>>();
    passC_k<<<grid, 256>>>(x, y);
}

// round 8
// speedup vs baseline: 1.4054x; 1.0417x over previous
#include <cuda_runtime.h>
#include <math.h>

// S4D real SSM, v4: single fused kernel (chunk aggregate -> decoupled-lookback
// prefix -> output recurrence), packed fma.rn.f32x2 throughout.
//  - NC=32 chunks of LC=128; grid (32,16)=512 blocks of 256 thr, all resident
//  - x tile loaded once per block as packed {x,x} ull (no per-step pack)
//  - cross-block sync: per-(chunk,group) flag, 0=none 1=aggregate 2=prefix

#define LEN 4096
#define CH  512
#define S   64
#define NC  32
#define LC  128
#define CS  (CH*S)
#define DT  (1.0/4096.0)

#define NPK 4              // f32x2 pairs per lane (8 states)
#define SPL 8              // states per lane
#define CPW 4              // channels per warp
#define CPB 32             // channels per block
#define NG  (CH/CPB)       // 16 channel groups

typedef unsigned long long ull;

__device__ float g_a [CS];      // exp(A*dt)
__device__ float g_cb[CS];      // C * Bd
__device__ float g_dc[CS];      // exp(A*dt*LC)  (chunk decay)
__device__ float g_v [NC*CS];   // chunk aggregates
__device__ float g_p [NC*CS];   // inclusive chunk prefixes
__device__ int   g_flag[NC*NG]; // 0 none / 1 aggregate / 2 prefix

// ---- packed f32x2 helpers (Blackwell FFMA2, PTX-only) ---------------------
__device__ __forceinline__ ull pack2(float x, float y) {
    ull r; asm("mov.b64 %0, {%1, %2};" : "=l"(r) : "f"(x), "f"(y)); return r;
}
__device__ __forceinline__ ull fma2(ull a, ull b, ull c) {
    ull d; asm("fma.rn.f32x2 %0, %1, %2, %3;" : "=l"(d) : "l"(a), "l"(b), "l"(c)); return d;
}
__device__ __forceinline__ ull mul2(ull a, ull b) {
    ull d; asm("mul.rn.f32x2 %0, %1, %2;" : "=l"(d) : "l"(a), "l"(b)); return d;
}
__device__ __forceinline__ float hsum2(ull v) {
    float lo, hi; asm("mov.b64 {%0, %1}, %2;" : "=f"(lo), "=f"(hi) : "l"(v));
    return lo + hi;
}

// ---------------------------------------------------------------- precompute
// also resets the lookback flags for each graph replay (runs before fused_k)
__global__ void precompute_k(const float* __restrict__ lognegA,
                             const float* __restrict__ B,
                             const float* __restrict__ C)
{
    int i = blockIdx.x * blockDim.x + threadIdx.x;
    if (i < NC * NG) g_flag[i] = 0;
    if (i >= CS) return;
    double A  = -exp((double)lognegA[i]);
    double ad = A * DT;
    double Bd = expm1(ad) / A * (double)B[i];
    g_a [i] = (float)exp(ad);
    g_cb[i] = (float)((double)C[i] * Bd);
    g_dc[i] = (float)exp(ad * (double)LC);
}

// ---------------------------------------------------------------- fused scan
__global__ __launch_bounds__(256, 4)
void fused_k(const float* __restrict__ x, float* __restrict__ y)
{
    __shared__ ull sx[LC][CPB];          // packed {x,x} tile, 32 KB
    const int k     = blockIdx.x;        // chunk (ascending with bid per group)
    const int gb    = blockIdx.y;        // channel group
    const int cbase = gb * CPB;
    const int tid   = threadIdx.x;
    const int w     = tid >> 5;
    const int lane  = tid & 31;
    const int g     = lane >> 3;         // channel within warp
    const int q     = lane & 7;          // lane within 8-lane channel team
    const int l0    = k * LC;

    // ---- tile load: float4 from gmem, duplicate into packed ull smem
    #pragma unroll 4
    for (int i = tid; i < LC * CPB / 4; i += 256) {
        int lr = i >> 3, c4 = (i & 7) << 2;
        float4 v4 = *reinterpret_cast<const float4*>(x + (l0 + lr) * CH + cbase + c4);
        sx[lr][c4 + 0] = pack2(v4.x, v4.x);
        sx[lr][c4 + 1] = pack2(v4.y, v4.y);
        sx[lr][c4 + 2] = pack2(v4.z, v4.z);
        sx[lr][c4 + 3] = pack2(v4.w, v4.w);
    }
    __syncthreads();

    const int c     = cbase + w * CPW + g;
    const int sbase = c * S + q * SPL;
    const int chl   = w * CPW + g;

    ull a[NPK];
    const ull* aP = reinterpret_cast<const ull*>(g_a + sbase);
    #pragma unroll
    for (int t = 0; t < NPK; t++) a[t] = aP[t];

    // ---- phase 1: chunk aggregate (zero initial state)
    ull v[NPK] = {0ull, 0ull, 0ull, 0ull};
    #pragma unroll 8
    for (int l = 0; l < LC; l++) {
        ull xx = sx[l][chl];
        #pragma unroll
        for (int t = 0; t < NPK; t++) v[t] = fma2(a[t], v[t], xx);
    }

    if (k > 0) {                          // publish aggregate
        ull* vP = reinterpret_cast<ull*>(g_v + k * CS + sbase);
        #pragma unroll
        for (int t = 0; t < NPK; t++) vP[t] = v[t];
        __threadfence();
        __syncthreads();
        if (tid == 0) atomicExch(&g_flag[k * NG + gb], 1);
    }

    ull dc[NPK];
    const ull* dP = reinterpret_cast<const ull*>(g_dc + sbase);
    #pragma unroll
    for (int t = 0; t < NPK; t++) dc[t] = dP[t];

    // ---- phase 2: decoupled lookback -> h0 (state entering this chunk)
    ull h0[NPK] = {0ull, 0ull, 0ull, 0ull};
    if (k > 0) {
        const ull one = pack2(1.f, 1.f);
        ull dpow[NPK]  = {one, one, one, one};
        ull carry[NPK] = {0ull, 0ull, 0ull, 0ull};
        int j = k - 1;
        while (1) {
            int st = 0;
            if (lane == 0) {
                while ((st = atomicAdd(&g_flag[j * NG + gb], 0)) == 0) __nanosleep(40);
            }
            st = __shfl_sync(0xffffffffu, st, 0);
            __threadfence();
            if (st == 2) {                // predecessor prefix: terminate
                const ull* pP = reinterpret_cast<const ull*>(g_p + j * CS + sbase);
                #pragma unroll
                for (int t = 0; t < NPK; t++) carry[t] = fma2(dpow[t], __ldcg(pP + t), carry[t]);
                break;
            } else {                      // aggregate only: accumulate, step back
                const ull* jv = reinterpret_cast<const ull*>(g_v + j * CS + sbase);
                #pragma unroll
                for (int t = 0; t < NPK; t++) carry[t] = fma2(dpow[t], __ldcg(jv + t), carry[t]);
                #pragma unroll
                for (int t = 0; t < NPK; t++) dpow[t] = mul2(dpow[t], dc[t]);
                if (--j < 0) break;       // unreachable (chunk 0 publishes 2)
            }
        }
        #pragma unroll
        for (int t = 0; t < NPK; t++) h0[t] = carry[t];
    }

    // ---- publish inclusive prefix P_k = dc*h0 + v (skip for last chunk)
    if (k < NC - 1) {
        ull* pP = reinterpret_cast<ull*>(g_p + k * CS + sbase);
        #pragma unroll
        for (int t = 0; t < NPK; t++) pP[t] = fma2(dc[t], h0[t], v[t]);
        __threadfence();
        __syncthreads();
        if (tid == 0) atomicExch(&g_flag[k * NG + gb], 2);
    }

    // ---- phase 3: output recurrence from h0
    ull cb[NPK];
    const ull* cbP = reinterpret_cast<const ull*>(g_cb + sbase);
    #pragma unroll
    for (int t = 0; t < NPK; t++) cb[t] = cbP[t];
    ull h[NPK];
    #pragma unroll
    for (int t = 0; t < NPK; t++) h[t] = h0[t];

    #pragma unroll 2
    for (int r = 0; r < LC / 8; r++) {
        float p[8];
        #pragma unroll
        for (int j = 0; j < 8; j++) {
            ull xx = sx[r * 8 + j][chl];
            #pragma unroll
            for (int t = 0; t < NPK; t++) h[t] = fma2(a[t], h[t], xx);
            ull acc = mul2(cb[0], h[0]);
            #pragma unroll
            for (int t = 1; t < NPK; t++) acc = fma2(cb[t], h[t], acc);
            p[j] = hsum2(acc);
        }
        // 3-stage register-halving butterfly over the 8-lane team:
        // afterwards lane q holds the finished output for step r*8+q
        #pragma unroll
        for (int d = 4; d >= 1; d >>= 1) {
            #pragma unroll
            for (int m = 0; m < d; m++) {
                bool  hi   = (q & d) != 0;
                float send = hi ? p[m] : p[m + d];
                float got  = __shfl_xor_sync(0xffffffffu, send, d);
                p[m] = (hi ? p[m + d] : p[m]) + got;
            }
        }
        y[(l0 + r * 8 + q) * CH + c] = p[0];
    }
}

// ---------------------------------------------------------------- launch
extern "C" void kernel_launch(void* const* d_in, const int* in_sizes, int n_in,
                              void* d_out, int out_size)
{
    const float* x       = (const float*)d_in[0];
    const float* lognegA = (const float*)d_in[1];
    const float* B       = (const float*)d_in[2];
    const float* C       = (const float*)d_in[3];
    float*       y       = (float*)d_out;

    precompute_k<<<CS / 256, 256>>>(lognegA, B, C);   // also resets flags
    dim3 grid(NC, NG);
    fused_k<<<grid, 256>>>(x, y);
}